// round 4
// baseline (speedup 1.0000x reference)
#include <cuda_runtime.h>
#include <math.h>

#define SOM_DIM   512
#define SOM_MN    65536          // 256*256 rows
#define ROWS_PER_BLK 8           // 8 warps per block, one row per warp
#define N_BLOCKS (SOM_MN / ROWS_PER_BLK)   // 8192

__device__ unsigned long long g_key;     // packed (dist_bits<<32 | row), global min
__device__ float g_rate;
__device__ float g_inv2s2;

// ---- L2 evict-last load via cache_hint policy (v4.f32-compatible) ----------
__device__ __forceinline__ unsigned long long evict_last_policy() {
    unsigned long long pol;
    asm("createpolicy.fractional.L2::evict_last.b64 %0, 1.0;" : "=l"(pol));
    return pol;
}
__device__ __forceinline__ float4 ldg_evict_last(const float4* p,
                                                 unsigned long long pol) {
    float4 v;
    asm("ld.global.L2::cache_hint.v4.f32 {%0,%1,%2,%3}, [%4], %5;"
        : "=f"(v.x), "=f"(v.y), "=f"(v.z), "=f"(v.w) : "l"(p), "l"(pol));
    return v;
}

// ---------------------------------------------------------------------------
// Init: reset argmin key, precompute iteration scalars (only FP64 here).
// ---------------------------------------------------------------------------
__global__ void som_init_kernel(const int* __restrict__ it_p)
{
    g_key = 0xFFFFFFFFFFFFFFFFULL;
    const int it = *it_p;
    const double decay   = exp(-(double)it / 2000.0);   // N_ITER
    const double sigma_t = 128.0 * decay;               // SIGMA * decay
    g_rate   = (float)(0.5 * decay);                    // ALPHA * decay
    g_inv2s2 = (float)(1.0 / (2.0 * sigma_t * sigma_t));
}

// ---------------------------------------------------------------------------
// Pass 1: per-row squared distance (argmin of sqrt == argmin of sum).
// One warp per row; loads front-batched (MLP=4/lane), W read with an
// evict-last L2 policy so it survives into pass 2. Block min -> atomicMin.
// ---------------------------------------------------------------------------
__global__ __launch_bounds__(256) void som_dist_kernel(
    const float* __restrict__ x, const float* __restrict__ w)
{
    __shared__ unsigned long long s_keys[ROWS_PER_BLK];
    const int lane = threadIdx.x & 31;
    const int warp = threadIdx.x >> 5;
    const int row  = blockIdx.x * ROWS_PER_BLK + warp;

    const float4* __restrict__ wr = (const float4*)(w + (size_t)row * SOM_DIM);
    const float4* __restrict__ xr = (const float4*)x;

    const unsigned long long pol = evict_last_policy();

    float4 wv[4], xv[4];
#pragma unroll
    for (int i = 0; i < 4; i++)
        wv[i] = ldg_evict_last(&wr[lane + 32 * i], pol);
#pragma unroll
    for (int i = 0; i < 4; i++)
        xv[i] = __ldg(&xr[lane + 32 * i]);

    float a0 = 0.f, a1 = 0.f, a2 = 0.f, a3 = 0.f;
#pragma unroll
    for (int i = 0; i < 4; i++) {
        float d0 = xv[i].x - wv[i].x + 1e-6f;
        float d1 = xv[i].y - wv[i].y + 1e-6f;
        float d2 = xv[i].z - wv[i].z + 1e-6f;
        float d3 = xv[i].w - wv[i].w + 1e-6f;
        a0 += d0 * d0;  a1 += d1 * d1;
        a2 += d2 * d2;  a3 += d3 * d3;
    }
    float acc = (a0 + a1) + (a2 + a3);
#pragma unroll
    for (int o = 16; o > 0; o >>= 1)
        acc += __shfl_xor_sync(0xFFFFFFFFu, acc, o);

    if (lane == 0) {
        // acc >= 0 so fp32 bit pattern is order-preserving as uint.
        unsigned long long key =
            ((unsigned long long)__float_as_uint(acc) << 32) | (unsigned)row;
        s_keys[warp] = key;
    }
    __syncthreads();
    if (threadIdx.x == 0) {
        unsigned long long k = s_keys[0];
#pragma unroll
        for (int i = 1; i < ROWS_PER_BLK; i++)
            k = min(k, s_keys[i]);
        atomicMin(&g_key, k);
    }
}

// ---------------------------------------------------------------------------
// Pass 2: warp-per-row, descending rows (consume freshest L2 lines first).
// W read evict-first (.cs), out stored evict-first (.cs) so the output
// stream doesn't evict the W lines pinned by pass 1.
// Per-warp coefficient (fp32 sqrt/exp) overlaps the front-batched loads.
// ---------------------------------------------------------------------------
__global__ __launch_bounds__(256) void som_update_kernel(
    const float* __restrict__ x, const float* __restrict__ w,
    const float* __restrict__ loc, float* __restrict__ out, int has_idx_tail)
{
    const int lane = threadIdx.x & 31;
    const int warp = threadIdx.x >> 5;
    const int row  = (SOM_MN - 1) - (blockIdx.x * ROWS_PER_BLK + warp);

    const float4* __restrict__ wr = (const float4*)(w + (size_t)row * SOM_DIM);
    const float4* __restrict__ xr = (const float4*)x;
    float4* __restrict__ orow = (float4*)(out + (size_t)row * SOM_DIM);

    // Front-batch all memory (8 independent loads per lane).
    float4 wv[4], xv[4];
#pragma unroll
    for (int i = 0; i < 4; i++)
        wv[i] = __ldcs(&wr[lane + 32 * i]);
#pragma unroll
    for (int i = 0; i < 4; i++)
        xv[i] = __ldg(&xr[lane + 32 * i]);

    // Per-row coefficient, computed redundantly per lane (cheap fp32/MUFU);
    // overlaps the load latency above.
    const int   bidx = (int)(g_key & 0xFFFFFFFFu);
    const float b0 = __ldg(&loc[2 * bidx]);
    const float b1 = __ldg(&loc[2 * bidx + 1]);
    const float l0 = __ldg(&loc[2 * row]);
    const float l1 = __ldg(&loc[2 * row + 1]);
    const float d0 = b0 - l0 + 1e-6f;
    const float d1 = b1 - l1 + 1e-6f;
    const float ld = sqrtf(d0 * d0 + d1 * d1);      // match sqrt-then-square
    const float c  = g_rate * expf(-(ld * ld) * g_inv2s2);

#pragma unroll
    for (int i = 0; i < 4; i++) {
        float4 o;
        o.x = wv[i].x + c * (xv[i].x - wv[i].x);
        o.y = wv[i].y + c * (xv[i].y - wv[i].y);
        o.z = wv[i].z + c * (xv[i].z - wv[i].z);
        o.w = wv[i].w + c * (xv[i].w - wv[i].w);
        __stcs(&orow[lane + 32 * i], o);
    }

    if (has_idx_tail && blockIdx.x == 0 && threadIdx.x == 0)
        out[(size_t)SOM_MN * SOM_DIM] = (float)bidx;
}

extern "C" void kernel_launch(void* const* d_in, const int* in_sizes, int n_in,
                              void* d_out, int out_size)
{
    const float* x   = (const float*)d_in[0];   // (512,)
    const float* w   = (const float*)d_in[1];   // (65536, 512)
    const float* loc = (const float*)d_in[2];   // (65536, 2)
    const int*   it  = (const int*)d_in[3];     // scalar
    float* out = (float*)d_out;

    const int has_tail = (out_size > SOM_MN * SOM_DIM) ? 1 : 0;

    som_init_kernel<<<1, 1>>>(it);
    som_dist_kernel<<<N_BLOCKS, 256>>>(x, w);
    som_update_kernel<<<N_BLOCKS, 256>>>(x, w, loc, out, has_tail);
}